// round 4
// baseline (speedup 1.0000x reference)
#include <cuda_runtime.h>

#define UNITS 128
#define WIN   1024
#define JT    4              // j-rows per block
#define NBLK  (WIN / JT)     // 256 blocks -> 2 CTAs per SM
#define KS    16             // k-slice per warp (8 warps * 16 = 128)

// Global accumulators; last block resets them so graph replays stay correct.
__device__ float        g_s[UNITS];
__device__ float        g_ws[UNITS];
__device__ unsigned int g_count;

// ---------------------------------------------------------------------------
// Fused, split-K kernel (2 CTAs/SM for latency hiding).
//   logit[j,u] = sum_k fs[j,k]*w_hi[k,u] + (fs[j].input)*w_dot[u]
//   out[u]     = sum_j e(logit)*fs[j,u] / sum_j e(logit)
// (softmax shift-invariant; |logit| small so no max-subtraction — fp32-safe)
//
// 256 blocks x 256 threads, JT=4 j-rows per block. Warp w owns k in
// [16w,16w+16): 16 independent LDG.128 of its w slice into registers
// (full MLP, each w element touched once per block), partials for the 4 j
// rows, cross-warp reduce through smem, per-u atomics, last-block epilogue.
// ---------------------------------------------------------------------------
__global__ __launch_bounds__(256, 2) void rsa_fused3_kernel(
    const float* __restrict__ input,   // [128]
    const float* __restrict__ state,   // [128][1024]
    const float* __restrict__ w,       // [257][128]
    float* __restrict__ out)           // [128]
{
    __shared__ float fs_s[JT][UNITS];        // fs tile [jj][k]      (2 KB)
    __shared__ float inp_s[UNITS];           //                      (0.5 KB)
    __shared__ float d_s[JT];                // fs[j].input per j
    __shared__ float part[8][JT][UNITS];     // split-K partials     (16 KB)
    __shared__ bool  is_last;

    const int tid  = threadIdx.x;
    const int wid  = tid >> 5;
    const int lane = tid & 31;
    const int u0   = lane * 4;
    const int j0   = blockIdx.x * JT;
    const int k0   = wid * KS;

    // 1) Front-load this warp's w slice: 16 independent LDG.128 (full MLP).
    float4 wreg[KS];
    #pragma unroll
    for (int k = 0; k < KS; ++k)
        wreg[k] = *reinterpret_cast<const float4*>(&w[(k0 + k) * UNITS + u0]);

    if (tid < UNITS) inp_s[tid] = input[tid];

    // fs[j,k] = state[k, j+1] (j < 1023) else input[k]; JT*UNITS = 512 elems
    #pragma unroll
    for (int idx = tid; idx < JT * UNITS; idx += 256) {
        int k  = idx >> 2;
        int jj = idx & (JT - 1);
        int j  = j0 + jj;
        fs_s[jj][k] = (j < WIN - 1) ? state[k * WIN + j + 1] : input[k];
    }
    __syncthreads();

    // 2) d_j = fs[j].input — warps 0..3 handle j = wid.
    if (wid < JT) {
        float dp = 0.f;
        #pragma unroll
        for (int k = lane; k < UNITS; k += 32)
            dp += fs_s[wid][k] * inp_s[k];
        #pragma unroll
        for (int off = 16; off; off >>= 1)
            dp += __shfl_xor_sync(0xffffffffu, dp, off);
        if (lane == 0) d_s[wid] = dp;
    }

    // 3) Split-K partial GEMM: acc[j][u0..3] over this warp's 16 k's.
    float4 acc[JT];
    #pragma unroll
    for (int j = 0; j < JT; ++j) acc[j] = make_float4(0.f, 0.f, 0.f, 0.f);

    #pragma unroll
    for (int k = 0; k < KS; ++k) {
        const float4 wv = wreg[k];
        #pragma unroll
        for (int j = 0; j < JT; ++j) {
            float f = fs_s[j][k0 + k];          // smem broadcast
            acc[j].x += f * wv.x;
            acc[j].y += f * wv.y;
            acc[j].z += f * wv.z;
            acc[j].w += f * wv.w;
        }
    }
    #pragma unroll
    for (int j = 0; j < JT; ++j)
        *reinterpret_cast<float4*>(&part[wid][j][u0]) = acc[j];
    __syncthreads();

    // 4) Cross-warp reduce -> logit -> e. 128 active threads: slot = (j, u0),
    //    j = tid>>5 in [0,4), u0 = (tid&31)*4. e overlays part[0] (owner-
    //    exclusive read-then-write, safe).
    if (tid < JT * 32) {
        const int j  = tid >> 5;
        const int uu = (tid & 31) * 4;
        float4 sum = make_float4(0.f, 0.f, 0.f, 0.f);
        #pragma unroll
        for (int r = 0; r < 8; ++r) {
            float4 p = *reinterpret_cast<const float4*>(&part[r][j][uu]);
            sum.x += p.x; sum.y += p.y; sum.z += p.z; sum.w += p.w;
        }
        const float  dj = d_s[j];
        const float4 wd = *reinterpret_cast<const float4*>(&w[2 * UNITS * UNITS + uu]);
        float4 e;
        e.x = __expf(sum.x + dj * wd.x);
        e.y = __expf(sum.y + dj * wd.y);
        e.z = __expf(sum.z + dj * wd.z);
        e.w = __expf(sum.w + dj * wd.w);
        *reinterpret_cast<float4*>(&part[0][j][uu]) = e;
    }
    __syncthreads();

    // 5) Per-u reduce over this block's JT j rows, one REDG pair per u.
    if (tid < UNITS) {
        float s = 0.f, ws = 0.f;
        #pragma unroll
        for (int r = 0; r < JT; ++r) {
            float e = part[0][r][tid];
            s  += e;
            ws += e * fs_s[r][tid];
        }
        atomicAdd(&g_s[tid],  s);
        atomicAdd(&g_ws[tid], ws);
    }
    __threadfence();
    __syncthreads();

    if (tid == 0)
        is_last = (atomicAdd(&g_count, 1u) == (unsigned)(NBLK - 1));
    __syncthreads();

    if (is_last) {
        if (tid < UNITS) {
            float S  = atomicAdd(&g_s[tid],  0.f);   // L2-coherent reads
            float WS = atomicAdd(&g_ws[tid], 0.f);
            out[tid] = WS / S;
            g_s[tid]  = 0.f;                          // reset for next replay
            g_ws[tid] = 0.f;
        }
        __syncthreads();
        if (tid == 0) g_count = 0u;
    }
}

// ---------------------------------------------------------------------------
extern "C" void kernel_launch(void* const* d_in, const int* in_sizes, int n_in,
                              void* d_out, int out_size) {
    const float* input = (const float*)d_in[0];   // (1, 128)
    const float* state = (const float*)d_in[1];   // (128, 1024)
    const float* w     = (const float*)d_in[2];   // (257, 128)
    // d_in[3] = b cancels in the softmax -> unused
    float* out = (float*)d_out;                   // (1, 128)

    rsa_fused3_kernel<<<NBLK, 256>>>(input, state, w, out);
}

// round 5
// speedup vs baseline: 1.2071x; 1.2071x over previous
#include <cuda_runtime.h>
#include <cstdint>

#define UNITS 128
#define WIN   1024
#define JT    8              // j-rows per block
#define NBLK  (WIN / JT)     // 128 blocks (R4's 256 regressed -> reverted)
#define NW    16             // warps per block
#define KS    (UNITS / NW)   // 8 k's per warp

// Global accumulators; last block resets them so graph replays stay correct.
__device__ float        g_s[UNITS];
__device__ float        g_ws[UNITS];
__device__ unsigned int g_count;

// Packed fp32x2 helpers (sm_103a): 2 MACs per fma-pipe issue.
#define PACK2(d, lo, hi)   asm("mov.b64 %0, {%1, %2};" : "=l"(d) : "f"(lo), "f"(hi))
#define UNPACK2(lo, hi, v) asm("mov.b64 {%0, %1}, %2;" : "=f"(lo), "=f"(hi) : "l"(v))
#define FMA2(d, a, b, c)   asm("fma.rn.f32x2 %0, %1, %2, %3;" : "=l"(d) : "l"(a), "l"(b), "l"(c))

// ---------------------------------------------------------------------------
// Fused split-K kernel, 128 blocks x 512 threads (16 warps).
//   logit[j,u] = sum_k fs[j,k]*w_hi[k,u] + (fs[j].input)*w_dot[u]
//   out[u]     = sum_j e(logit)*fs[j,u] / sum_j e(logit)
// (softmax shift-invariant; |logit| small -> no max-subtraction, fp32-safe)
//
// Warp w owns k in [8w, 8w+8): 8 independent LDG.128 of its w slice into
// registers. GEMM runs on the packed f32x2 pipe: j-pairs packed in 64-bit
// accumulators, fs stored transposed [k][j] so a broadcast float2 LDS gives
// the packed multiplier directly. Two-stage smem reduce across the 16 warps,
// then exp, per-u block reduce, global atomics, last-block epilogue.
// ---------------------------------------------------------------------------
__global__ __launch_bounds__(512, 1) void rsa_fused4_kernel(
    const float* __restrict__ input,   // [128]
    const float* __restrict__ state,   // [128][1024]
    const float* __restrict__ w,       // [257][128]
    float* __restrict__ out)           // [128]
{
    __shared__ float fs_t[UNITS][JT];        // fs transposed [k][j]  (4 KB)
    __shared__ float inp_s[UNITS];
    __shared__ float d_s[JT];                // fs[j].input
    __shared__ float part[NW / 2][JT][UNITS];// stage-reduce partials (32 KB)
    __shared__ bool  is_last;

    const int tid  = threadIdx.x;
    const int wid  = tid >> 5;
    const int lane = tid & 31;
    const int u0   = lane * 4;
    const int j0   = blockIdx.x * JT;
    const int k0   = wid * KS;

    // 1) Front-load this warp's w slice: 8 independent LDG.128 (full MLP).
    float4 wreg[KS];
    #pragma unroll
    for (int k = 0; k < KS; ++k)
        wreg[k] = *reinterpret_cast<const float4*>(&w[(k0 + k) * UNITS + u0]);

    if (tid < UNITS) inp_s[tid] = input[tid];

    // fs[j,k] = state[k, j+1] (j < 1023) else input[k]; stored transposed.
    #pragma unroll
    for (int idx = tid; idx < JT * UNITS; idx += 512) {
        int k  = idx >> 3;
        int jj = idx & (JT - 1);
        int j  = j0 + jj;
        fs_t[k][jj] = (j < WIN - 1) ? state[k * WIN + j + 1] : input[k];
    }
    __syncthreads();

    // 2) d_j = fs[j].input — warps 0..7 handle j = wid.
    if (wid < JT) {
        float dp = 0.f;
        #pragma unroll
        for (int k = lane; k < UNITS; k += 32)
            dp += fs_t[k][wid] * inp_s[k];
        #pragma unroll
        for (int off = 16; off; off >>= 1)
            dp += __shfl_xor_sync(0xffffffffu, dp, off);
        if (lane == 0) d_s[wid] = dp;
    }

    // 3) Packed GEMM: acc[jp][c] = ( sum over (j=2jp,u0+c), sum over (j=2jp+1,u0+c) ).
    uint64_t acc[JT / 2][4];
    #pragma unroll
    for (int jp = 0; jp < JT / 2; ++jp)
        #pragma unroll
        for (int c = 0; c < 4; ++c) acc[jp][c] = 0ull;   // bits(0,0) = (0.f,0.f)

    #pragma unroll
    for (int k = 0; k < KS; ++k) {
        const float4 wv = wreg[k];
        uint64_t wxx, wyy, wzz, www;
        PACK2(wxx, wv.x, wv.x);
        PACK2(wyy, wv.y, wv.y);
        PACK2(wzz, wv.z, wv.z);
        PACK2(www, wv.w, wv.w);
        const float2* frow = reinterpret_cast<const float2*>(&fs_t[k0 + k][0]);
        #pragma unroll
        for (int jp = 0; jp < JT / 2; ++jp) {
            float2  f2 = frow[jp];               // broadcast LDS.64, conflict-free
            uint64_t fp;
            PACK2(fp, f2.x, f2.y);
            FMA2(acc[jp][0], fp, wxx, acc[jp][0]);
            FMA2(acc[jp][1], fp, wyy, acc[jp][1]);
            FMA2(acc[jp][2], fp, wzz, acc[jp][2]);
            FMA2(acc[jp][3], fp, www, acc[jp][3]);
        }
    }

    // 4) Two-stage cross-warp reduce.
    // Stage A: warps 8..15 store their partials to part[w-8].
    if (wid >= NW / 2) {
        #pragma unroll
        for (int jp = 0; jp < JT / 2; ++jp) {
            float4 p0, p1;
            UNPACK2(p0.x, p1.x, acc[jp][0]);
            UNPACK2(p0.y, p1.y, acc[jp][1]);
            UNPACK2(p0.z, p1.z, acc[jp][2]);
            UNPACK2(p0.w, p1.w, acc[jp][3]);
            *reinterpret_cast<float4*>(&part[wid - NW / 2][2 * jp + 0][u0]) = p0;
            *reinterpret_cast<float4*>(&part[wid - NW / 2][2 * jp + 1][u0]) = p1;
        }
    }
    __syncthreads();
    // Stage B: warps 0..7 fold their partials into part[wid].
    if (wid < NW / 2) {
        #pragma unroll
        for (int jp = 0; jp < JT / 2; ++jp) {
            float4 a0, a1;
            UNPACK2(a0.x, a1.x, acc[jp][0]);
            UNPACK2(a0.y, a1.y, acc[jp][1]);
            UNPACK2(a0.z, a1.z, acc[jp][2]);
            UNPACK2(a0.w, a1.w, acc[jp][3]);
            float4 p0 = *reinterpret_cast<const float4*>(&part[wid][2 * jp + 0][u0]);
            float4 p1 = *reinterpret_cast<const float4*>(&part[wid][2 * jp + 1][u0]);
            p0.x += a0.x; p0.y += a0.y; p0.z += a0.z; p0.w += a0.w;
            p1.x += a1.x; p1.y += a1.y; p1.z += a1.z; p1.w += a1.w;
            *reinterpret_cast<float4*>(&part[wid][2 * jp + 0][u0]) = p0;
            *reinterpret_cast<float4*>(&part[wid][2 * jp + 1][u0]) = p1;
        }
    }
    __syncthreads();

    // Stage C: 256 threads own (j, u0): sum 8 partials -> logit -> e.
    // e overlays part[0] (owner-exclusive read-then-write, safe).
    if (tid < JT * 32) {
        const int j  = tid >> 5;
        const int uu = (tid & 31) * 4;
        float4 sum = make_float4(0.f, 0.f, 0.f, 0.f);
        #pragma unroll
        for (int r = 0; r < NW / 2; ++r) {
            float4 p = *reinterpret_cast<const float4*>(&part[r][j][uu]);
            sum.x += p.x; sum.y += p.y; sum.z += p.z; sum.w += p.w;
        }
        const float  dj = d_s[j];
        const float4 wd = *reinterpret_cast<const float4*>(&w[2 * UNITS * UNITS + uu]);
        float4 e;
        e.x = __expf(sum.x + dj * wd.x);
        e.y = __expf(sum.y + dj * wd.y);
        e.z = __expf(sum.z + dj * wd.z);
        e.w = __expf(sum.w + dj * wd.w);
        *reinterpret_cast<float4*>(&part[0][j][uu]) = e;
    }
    __syncthreads();

    // 5) Per-u reduce over this block's 8 j rows, one REDG pair per u.
    if (tid < UNITS) {
        float s = 0.f, ws = 0.f;
        #pragma unroll
        for (int r = 0; r < JT; ++r) {
            float e = part[0][r][tid];
            s  += e;
            ws += e * fs_t[tid][r];
        }
        atomicAdd(&g_s[tid],  s);
        atomicAdd(&g_ws[tid], ws);
    }
    __threadfence();
    __syncthreads();

    if (tid == 0)
        is_last = (atomicAdd(&g_count, 1u) == (unsigned)(NBLK - 1));
    __syncthreads();

    if (is_last) {
        if (tid < UNITS) {
            float S  = atomicAdd(&g_s[tid],  0.f);   // L2-coherent reads
            float WS = atomicAdd(&g_ws[tid], 0.f);
            out[tid] = WS / S;
            g_s[tid]  = 0.f;                          // reset for next replay
            g_ws[tid] = 0.f;
        }
        __syncthreads();
        if (tid == 0) g_count = 0u;
    }
}

// ---------------------------------------------------------------------------
extern "C" void kernel_launch(void* const* d_in, const int* in_sizes, int n_in,
                              void* d_out, int out_size) {
    const float* input = (const float*)d_in[0];   // (1, 128)
    const float* state = (const float*)d_in[1];   // (128, 1024)
    const float* w     = (const float*)d_in[2];   // (257, 128)
    // d_in[3] = b cancels in the softmax -> unused
    float* out = (float*)d_out;                   // (1, 128)

    rsa_fused4_kernel<<<NBLK, 512>>>(input, state, w, out);
}

// round 7
// speedup vs baseline: 1.5000x; 1.2426x over previous
#include <cuda_runtime.h>

#define UNITS 128
#define WIN   1024
#define JT    8              // j-rows per block
#define NBLK  (WIN / JT)     // 128 blocks (best measured topology)
#define KS    16             // k-slice per warp (8 warps * 16 = 128)

// Global accumulators; last block resets them so graph replays stay correct.
__device__ float        g_s[UNITS];
__device__ float        g_ws[UNITS];
__device__ unsigned int g_count;

// ---------------------------------------------------------------------------
// Fused split-K kernel, critical-path-minimized.
// Identity: logit[j,u] = sum_k fs[j,k]*w_hi[k,u] + (fs[j].input)*w_dot[u]
//                      = sum_k fs[j,k]*(w_hi[k,u] + input[k]*w_dot[u])
// so the dot-product term folds into the GEMM weights (w_eff), deleting the
// whole d_j stage from the serial chain. Softmax is shift-invariant and
// |logit| is small -> no max subtraction (fp32-safe).
//
// 128 blocks x 256 threads. Warp w owns k in [16w,16w+16): 16 independent
// LDG.128 into registers, folded to w_eff with direct input[] reads (no smem
// dependency), GEMM over the smem fs tile, one-stage cross-warp smem reduce,
// exp, per-u block reduce, REDG pair, fence-counted last-block epilogue.
// ---------------------------------------------------------------------------
__global__ __launch_bounds__(256, 1) void rsa_fused5_kernel(
    const float* __restrict__ input,   // [128]
    const float* __restrict__ state,   // [128][1024]
    const float* __restrict__ w,       // [257][128]
    float* __restrict__ out)           // [128]
{
    __shared__ float fs_s[JT][UNITS];        // fs tile [jj][k]      (4 KB)
    __shared__ float part[8][JT][UNITS];     // split-K partials     (32 KB)
    __shared__ bool  is_last;

    const int tid  = threadIdx.x;
    const int wid  = tid >> 5;
    const int lane = tid & 31;
    const int u0   = lane * 4;
    const int j0   = blockIdx.x * JT;
    const int k0   = wid * KS;

    // 1) Front-load: w_dot row, this warp's w slice (16 independent LDG.128),
    //    and this warp's input slice — all in flight together, no syncs.
    const float4 wd = *reinterpret_cast<const float4*>(&w[2 * UNITS * UNITS + u0]);
    float4 wreg[KS];
    #pragma unroll
    for (int k = 0; k < KS; ++k)
        wreg[k] = *reinterpret_cast<const float4*>(&w[(k0 + k) * UNITS + u0]);

    float ivf[KS];
    #pragma unroll
    for (int i = 0; i < KS / 4; ++i) {
        float4 iv = *reinterpret_cast<const float4*>(&input[k0 + 4 * i]);
        ivf[4 * i + 0] = iv.x;
        ivf[4 * i + 1] = iv.y;
        ivf[4 * i + 2] = iv.z;
        ivf[4 * i + 3] = iv.w;
    }

    // fs[j,k] = state[k, j+1] (j < 1023) else input[k]
    #pragma unroll
    for (int idx = tid; idx < JT * UNITS; idx += 256) {
        int k  = idx >> 3;
        int jj = idx & (JT - 1);
        int j  = j0 + jj;
        fs_s[jj][k] = (j < WIN - 1) ? state[k * WIN + j + 1] : input[k];
    }

    // 2) Fold: w_eff[k,u] = w_hi[k,u] + input[k]*w_dot[u]  (registers only)
    #pragma unroll
    for (int k = 0; k < KS; ++k) {
        wreg[k].x += ivf[k] * wd.x;
        wreg[k].y += ivf[k] * wd.y;
        wreg[k].z += ivf[k] * wd.z;
        wreg[k].w += ivf[k] * wd.w;
    }
    __syncthreads();

    // 3) Split-K partial GEMM: acc[j][u0..3] over this warp's 16 k's.
    float4 acc[JT];
    #pragma unroll
    for (int j = 0; j < JT; ++j) acc[j] = make_float4(0.f, 0.f, 0.f, 0.f);

    #pragma unroll
    for (int k = 0; k < KS; ++k) {
        const float4 wv = wreg[k];
        #pragma unroll
        for (int j = 0; j < JT; ++j) {
            float f = fs_s[j][k0 + k];          // smem broadcast, conflict-free
            acc[j].x += f * wv.x;
            acc[j].y += f * wv.y;
            acc[j].z += f * wv.z;
            acc[j].w += f * wv.w;
        }
    }
    #pragma unroll
    for (int j = 0; j < JT; ++j)
        *reinterpret_cast<float4*>(&part[wid][j][u0]) = acc[j];
    __syncthreads();

    // 4) Cross-warp reduce -> logit -> e. Thread owns (j=wid, u0). e overlays
    //    part[0] (owner-exclusive read-then-write, safe).
    {
        const int j = wid;
        float4 sum = make_float4(0.f, 0.f, 0.f, 0.f);
        #pragma unroll
        for (int r = 0; r < 8; ++r) {
            float4 p = *reinterpret_cast<const float4*>(&part[r][j][u0]);
            sum.x += p.x; sum.y += p.y; sum.z += p.z; sum.w += p.w;
        }
        float4 e;
        e.x = __expf(sum.x);
        e.y = __expf(sum.y);
        e.z = __expf(sum.z);
        e.w = __expf(sum.w);
        *reinterpret_cast<float4*>(&part[0][j][u0]) = e;
    }
    __syncthreads();

    // 5) Per-u reduce over this block's 8 j rows, one REDG pair per u.
    if (tid < UNITS) {
        float s = 0.f, ws = 0.f;
        #pragma unroll
        for (int r = 0; r < JT; ++r) {
            float e = part[0][r][tid];
            s  += e;
            ws += e * fs_s[r][tid];
        }
        atomicAdd(&g_s[tid],  s);
        atomicAdd(&g_ws[tid], ws);
    }
    __threadfence();
    __syncthreads();

    if (tid == 0)
        is_last = (atomicAdd(&g_count, 1u) == (unsigned)(NBLK - 1));
    __syncthreads();

    if (is_last) {
        if (tid < UNITS) {
            // count observed => every block's fence retired => REDGs are in L2.
            // .cg loads bypass (launch-stale) L1 and read L2 directly.
            float S  = __ldcg(&g_s[tid]);
            float WS = __ldcg(&g_ws[tid]);
            out[tid] = WS / S;
            g_s[tid]  = 0.f;                  // reset for next graph replay
            g_ws[tid] = 0.f;
        }
        __syncthreads();
        if (tid == 0) g_count = 0u;
    }
}

// ---------------------------------------------------------------------------
extern "C" void kernel_launch(void* const* d_in, const int* in_sizes, int n_in,
                              void* d_out, int out_size) {
    const float* input = (const float*)d_in[0];   // (1, 128)
    const float* state = (const float*)d_in[1];   // (128, 1024)
    const float* w     = (const float*)d_in[2];   // (257, 128)
    // d_in[3] = b cancels in the softmax -> unused
    float* out = (float*)d_out;                   // (1, 128)

    rsa_fused5_kernel<<<NBLK, 256>>>(input, state, w, out);
}